// round 8
// baseline (speedup 1.0000x reference)
#include <cuda_runtime.h>

#define TSTEPS 7
#define NSLOT 39   // per-warp u64 slots: 0..27 hup (+jjd park +acts park), 28..34 jj, 35..38 obs
typedef unsigned long long u64;

// ---- f32x2 packed helpers (sm_100+ PTX) ----
__device__ __forceinline__ u64 pack2(float lo, float hi) {
    u64 r; asm("mov.b64 %0, {%1, %2};" : "=l"(r) : "f"(lo), "f"(hi)); return r;
}
__device__ __forceinline__ u64 dup2(float v) {
    u64 r; asm("mov.b64 %0, {%1, %1};" : "=l"(r) : "f"(v)); return r;
}
__device__ __forceinline__ void unpack2(u64 p, float& lo, float& hi) {
    asm("mov.b64 {%0, %1}, %2;" : "=f"(lo), "=f"(hi) : "l"(p));
}
__device__ __forceinline__ u64 fma2(u64 a, u64 b, u64 c) {
    u64 d; asm("fma.rn.f32x2 %0, %1, %2, %3;" : "=l"(d) : "l"(a), "l"(b), "l"(c)); return d;
}
__device__ __forceinline__ float htanh(float x) {
    float r; asm("tanh.approx.f32 %0, %1;" : "=f"(r) : "f"(x)); return r;
}
__device__ __forceinline__ u64 tanh2(u64 p) {
    float lo, hi; unpack2(p, lo, hi);
    return pack2(htanh(lo), htanh(hi));
}

// scalar fallback for tail rows (cold path)
__device__ void scalar_row(int row,
                           const float* x,
                           const float* Wih_up, const float* Whh_up,
                           const float* bih_up, const float* bhh_up,
                           const float* W1, const float* b1,
                           const float* W2, const float* b2,
                           const float* Wih_dn, const float* Whh_dn,
                           const float* bih_dn, const float* bhh_dn,
                           const float* Wo, const float* bo,
                           float* out)
{
    float xr[18];
    for (int k = 0; k < 18; k++) xr[k] = x[(size_t)row * 18 + k];
    const float* obs = xr; const float* jj = xr + 4; const float* jjd = xr + 11;
    float h[4] = {0,0,0,0}, hup[TSTEPS][4];
    for (int s = 0; s < TSTEPS; s++) {
        int ti = TSTEPS - 1 - s;
        float pre[4];
        for (int i = 0; i < 4; i++) {
            float p = bih_up[i] + bhh_up[i];
            p = fmaf(Wih_up[i*2+0], jj[ti], p);
            p = fmaf(Wih_up[i*2+1], jjd[ti], p);
            for (int k = 0; k < 4; k++) p = fmaf(Whh_up[i*4+k], h[k], p);
            pre[i] = p;
        }
        for (int i = 0; i < 4; i++) { h[i] = htanh(pre[i]); hup[ti][i] = h[i]; }
    }
    float z[8]; for (int k = 0; k < 4; k++) { z[k] = obs[k]; z[4+k] = h[k]; }
    float h0[4];
    for (int i = 0; i < 4; i++) {
        float p = b1[i];
        for (int k = 0; k < 8; k++) p = fmaf(W1[i*8+k], z[k], p);
        h0[i] = htanh(p);
    }
    for (int i = 0; i < 4; i++) {
        float p = b2[i];
        for (int k = 0; k < 4; k++) p = fmaf(W2[i*4+k], h0[k], p);
        h[i] = htanh(p);
    }
    for (int t = 0; t < TSTEPS; t++) {
        float a = fmaf(Wo[4], jj[t], bo[0]);
        for (int k = 0; k < 4; k++) a = fmaf(Wo[k], h[k], a);
        out[(size_t)row * TSTEPS + t] = a;
        float hn[4];
        for (int i = 0; i < 4; i++) {
            float p = bih_dn[i] + bhh_dn[i];
            for (int k = 0; k < 4; k++) {
                p = fmaf(Wih_dn[i*4+k], hup[t][k], p);
                p = fmaf(Whh_dn[i*4+k], h[k], p);
            }
            hn[i] = htanh(p);
        }
        for (int i = 0; i < 4; i++) h[i] = hn[i];
    }
}

__global__ __launch_bounds__(128, 5)
void rec_policy_kernel(const float* __restrict__ x,
                       const float* __restrict__ Wih_up, const float* __restrict__ Whh_up,
                       const float* __restrict__ bih_up, const float* __restrict__ bhh_up,
                       const float* __restrict__ W1,     const float* __restrict__ b1,
                       const float* __restrict__ W2,     const float* __restrict__ b2,
                       const float* __restrict__ Wih_dn, const float* __restrict__ Whh_dn,
                       const float* __restrict__ bih_dn, const float* __restrict__ bhh_dn,
                       const float* __restrict__ Wo,     const float* __restrict__ bo,
                       float* __restrict__ out, int B)
{
    // Per-warp u64 region [NSLOT][32]. The x-gather float stage (4608B = slots 0..17)
    // overlays the hup slots: gather is fully consumed (packed into regs) before the
    // first hup write. jjd[t] parks in slot t*4 and is read at up-iter t immediately
    // before hup[t][0] is stored there (same-address program order). acts[t] parks in
    // slot t*4 again during the down phase after hu[t][0] is consumed.
    __shared__ u64 sm[4 * NSLOT * 32];

    const int tid  = threadIdx.x;
    const int lane = tid & 31;
    const int wid  = tid >> 5;
    u64* wsm = sm + wid * (NSLOT * 32);
    const int warpBase = (blockIdx.x * 128 + wid * 32) * 2;
    const int r0 = warpBase + lane * 2;

    const bool fast = (warpBase + 64 <= B);
    if (!fast) {
        if (r0 < B)     scalar_row(r0,   x, Wih_up, Whh_up, bih_up, bhh_up, W1, b1,
                                   W2, b2, Wih_dn, Whh_dn, bih_dn, bhh_dn, Wo, bo, out);
        if (r0 + 1 < B) scalar_row(r0+1, x, Wih_up, Whh_up, bih_up, bhh_up, W1, b1,
                                   W2, b2, Wih_dn, Whh_dn, bih_dn, bhh_dn, Wo, bo, out);
        return;
    }

    // ---- coalesced x gather into warp region (slots 0..17) ----
    {
        const float4* g  = reinterpret_cast<const float4*>(x + (size_t)warpBase * 18);
        float4*       s4 = reinterpret_cast<float4*>(wsm);
        #pragma unroll
        for (int r = 0; r < 9; r++) s4[r * 32 + lane] = g[r * 32 + lane];
    }
    __syncwarp();

    // ---- read own 36 floats, pack row-pair X[18] ----
    {
        float xb[36];
        const float4* sp = reinterpret_cast<const float4*>(
            reinterpret_cast<const float*>(wsm) + lane * 36);
        #pragma unroll
        for (int k = 0; k < 9; k++) {
            float4 v = sp[k];
            xb[4*k] = v.x; xb[4*k+1] = v.y; xb[4*k+2] = v.z; xb[4*k+3] = v.w;
        }
        __syncwarp();   // everyone done reading the stage before parks overwrite it

        // park: jj -> slots 28..34, jjd -> slot t*4, obs -> slots 35..38
        #pragma unroll
        for (int t = 0; t < TSTEPS; t++)
            wsm[(28 + t) * 32 + lane] = pack2(xb[4 + t], xb[18 + 4 + t]);
        #pragma unroll
        for (int t = 0; t < TSTEPS; t++)
            wsm[(t * 4) * 32 + lane] = pack2(xb[11 + t], xb[18 + 11 + t]);
        #pragma unroll
        for (int i = 0; i < 4; i++)
            wsm[(35 + i) * 32 + lane] = pack2(xb[i], xb[18 + i]);
    }

    u64 h[4];

    // ================= UP PHASE (packed) =================
    {
        float4 wiu01 = reinterpret_cast<const float4*>(Wih_up)[0];
        float4 wiu23 = reinterpret_cast<const float4*>(Wih_up)[1];
        float4 bi = reinterpret_cast<const float4*>(bih_up)[0];
        float4 bh = reinterpret_cast<const float4*>(bhh_up)[0];
        u64 wi0[4] = {dup2(wiu01.x), dup2(wiu01.z), dup2(wiu23.x), dup2(wiu23.z)};
        u64 wi1[4] = {dup2(wiu01.y), dup2(wiu01.w), dup2(wiu23.y), dup2(wiu23.w)};
        u64 bu[4]  = {dup2(bi.x+bh.x), dup2(bi.y+bh.y), dup2(bi.z+bh.z), dup2(bi.w+bh.w)};
        u64 whu[16];
        #pragma unroll
        for (int i = 0; i < 4; i++) {
            float4 w = reinterpret_cast<const float4*>(Whh_up)[i];
            whu[4*i+0] = dup2(w.x); whu[4*i+1] = dup2(w.y);
            whu[4*i+2] = dup2(w.z); whu[4*i+3] = dup2(w.w);
        }

        #pragma unroll
        for (int i = 0; i < 4; i++) h[i] = 0ull;

        #pragma unroll
        for (int s = 0; s < TSTEPS; s++) {
            const int ti = TSTEPS - 1 - s;
            u64 jjv = wsm[(28 + ti) * 32 + lane];
            u64 jdv = wsm[(ti * 4) * 32 + lane];   // jjd park; overwritten below by h[0]
            u64 pre[4];
            #pragma unroll
            for (int i = 0; i < 4; i++) {
                u64 p = fma2(wi0[i], jjv, bu[i]);
                p = fma2(wi1[i], jdv, p);
                p = fma2(whu[4*i+0], h[0], p);
                p = fma2(whu[4*i+1], h[1], p);
                p = fma2(whu[4*i+2], h[2], p);
                p = fma2(whu[4*i+3], h[3], p);
                pre[i] = p;
            }
            #pragma unroll
            for (int i = 0; i < 4; i++) {
                h[i] = tanh2(pre[i]);
                wsm[(ti * 4 + i) * 32 + lane] = h[i];
            }
        }
    }

    // ================= MLP PHASE (packed, stream once-used weights) =================
    {
        u64 z[8];
        #pragma unroll
        for (int k = 0; k < 4; k++) z[k] = wsm[(35 + k) * 32 + lane];   // obs park
        #pragma unroll
        for (int k = 0; k < 4; k++) z[4 + k] = h[k];

        float4 c1 = reinterpret_cast<const float4*>(b1)[0];
        float cb1[4] = {c1.x, c1.y, c1.z, c1.w};
        u64 h0[4];
        #pragma unroll
        for (int i = 0; i < 4; i++) {
            float4 a = reinterpret_cast<const float4*>(W1)[2*i];
            float4 b = reinterpret_cast<const float4*>(W1)[2*i+1];
            u64 p = dup2(cb1[i]);
            p = fma2(dup2(a.x), z[0], p); p = fma2(dup2(a.y), z[1], p);
            p = fma2(dup2(a.z), z[2], p); p = fma2(dup2(a.w), z[3], p);
            p = fma2(dup2(b.x), z[4], p); p = fma2(dup2(b.y), z[5], p);
            p = fma2(dup2(b.z), z[6], p); p = fma2(dup2(b.w), z[7], p);
            h0[i] = tanh2(p);
        }

        float4 c2 = reinterpret_cast<const float4*>(b2)[0];
        float cb2[4] = {c2.x, c2.y, c2.z, c2.w};
        #pragma unroll
        for (int i = 0; i < 4; i++) {
            float4 a = reinterpret_cast<const float4*>(W2)[i];
            u64 p = dup2(cb2[i]);
            p = fma2(dup2(a.x), h0[0], p); p = fma2(dup2(a.y), h0[1], p);
            p = fma2(dup2(a.z), h0[2], p); p = fma2(dup2(a.w), h0[3], p);
            h[i] = tanh2(p);
        }
    }

    // ================= DOWN PHASE (hybrid: wid scalar, whd packed) =================
    {
        float widm[16];                       // scalar input-hidden weights (shared by halves)
        #pragma unroll
        for (int i = 0; i < 4; i++) {
            float4 a = reinterpret_cast<const float4*>(Wih_dn)[i];
            widm[4*i+0] = a.x; widm[4*i+1] = a.y; widm[4*i+2] = a.z; widm[4*i+3] = a.w;
        }
        u64 whd[16];                          // packed hidden-hidden weights
        #pragma unroll
        for (int i = 0; i < 4; i++) {
            float4 b = reinterpret_cast<const float4*>(Whh_dn)[i];
            whd[4*i+0] = dup2(b.x); whd[4*i+1] = dup2(b.y);
            whd[4*i+2] = dup2(b.z); whd[4*i+3] = dup2(b.w);
        }
        float bds[4];
        {
            float4 bi = reinterpret_cast<const float4*>(bih_dn)[0];
            float4 bh = reinterpret_cast<const float4*>(bhh_dn)[0];
            bds[0] = bi.x+bh.x; bds[1] = bi.y+bh.y; bds[2] = bi.z+bh.z; bds[3] = bi.w+bh.w;
        }
        float4 wo_ = reinterpret_cast<const float4*>(Wo)[0];
        u64 wo0 = dup2(wo_.x), wo1 = dup2(wo_.y), wo2 = dup2(wo_.z), wo3 = dup2(wo_.w);
        u64 wojp = dup2(Wo[4]);
        u64 bovp = dup2(bo[0]);

        #pragma unroll
        for (int t = 0; t < TSTEPS; t++) {
            u64 hu0 = wsm[(t*4 + 0) * 32 + lane];
            u64 hu1 = wsm[(t*4 + 1) * 32 + lane];
            u64 hu2 = wsm[(t*4 + 2) * 32 + lane];
            u64 hu3 = wsm[(t*4 + 3) * 32 + lane];
            u64 jjv = wsm[(28 + t) * 32 + lane];

            // acts (packed) -> park in the just-consumed slot t*4
            u64 a = fma2(wojp, jjv, bovp);
            a = fma2(wo0, h[0], a);
            a = fma2(wo1, h[1], a);
            a = fma2(wo2, h[2], a);
            a = fma2(wo3, h[3], a);
            wsm[(t*4 + 0) * 32 + lane] = a;

            // scalar wid part on unpacked hu halves
            float hA0, hB0, hA1, hB1, hA2, hB2, hA3, hB3;
            unpack2(hu0, hA0, hB0); unpack2(hu1, hA1, hB1);
            unpack2(hu2, hA2, hB2); unpack2(hu3, hA3, hB3);

            u64 hn[4];
            #pragma unroll
            for (int i = 0; i < 4; i++) {
                float pA = bds[i];
                pA = fmaf(widm[4*i+0], hA0, pA);
                pA = fmaf(widm[4*i+1], hA1, pA);
                pA = fmaf(widm[4*i+2], hA2, pA);
                pA = fmaf(widm[4*i+3], hA3, pA);
                float pB = bds[i];
                pB = fmaf(widm[4*i+0], hB0, pB);
                pB = fmaf(widm[4*i+1], hB1, pB);
                pB = fmaf(widm[4*i+2], hB2, pB);
                pB = fmaf(widm[4*i+3], hB3, pB);
                u64 p = pack2(pA, pB);
                p = fma2(whd[4*i+0], h[0], p);
                p = fma2(whd[4*i+1], h[1], p);
                p = fma2(whd[4*i+2], h[2], p);
                p = fma2(whd[4*i+3], h[3], p);
                hn[i] = tanh2(p);
            }
            #pragma unroll
            for (int i = 0; i < 4; i++) h[i] = hn[i];
        }
    }

    // ---- output flush: parked acts -> 14 contiguous floats per thread ----
    {
        float a0[TSTEPS], a1[TSTEPS];
        #pragma unroll
        for (int t = 0; t < TSTEPS; t++)
            unpack2(wsm[(t*4 + 0) * 32 + lane], a0[t], a1[t]);
        float2* o = reinterpret_cast<float2*>(out + (size_t)r0 * TSTEPS);
        o[0] = make_float2(a0[0], a0[1]);
        o[1] = make_float2(a0[2], a0[3]);
        o[2] = make_float2(a0[4], a0[5]);
        o[3] = make_float2(a0[6], a1[0]);
        o[4] = make_float2(a1[1], a1[2]);
        o[5] = make_float2(a1[3], a1[4]);
        o[6] = make_float2(a1[5], a1[6]);
    }
}

extern "C" void kernel_launch(void* const* d_in, const int* in_sizes, int n_in,
                              void* d_out, int out_size)
{
    const float* x      = (const float*)d_in[0];
    const float* Wih_up = (const float*)d_in[1];
    const float* Whh_up = (const float*)d_in[2];
    const float* bih_up = (const float*)d_in[3];
    const float* bhh_up = (const float*)d_in[4];
    const float* W1     = (const float*)d_in[5];
    const float* b1     = (const float*)d_in[6];
    const float* W2     = (const float*)d_in[7];
    const float* b2     = (const float*)d_in[8];
    const float* Wih_dn = (const float*)d_in[9];
    const float* Whh_dn = (const float*)d_in[10];
    const float* bih_dn = (const float*)d_in[11];
    const float* bhh_dn = (const float*)d_in[12];
    const float* Wo     = (const float*)d_in[13];
    const float* bo     = (const float*)d_in[14];
    float* out = (float*)d_out;

    int B = in_sizes[0] / 18;
    int rowsPerBlock = 256;            // 128 threads x 2 rows
    int blocks = (B + rowsPerBlock - 1) / rowsPerBlock;
    rec_policy_kernel<<<blocks, 128>>>(x, Wih_up, Whh_up, bih_up, bhh_up,
                                       W1, b1, W2, b2,
                                       Wih_dn, Whh_dn, bih_dn, bhh_dn,
                                       Wo, bo, out, B);
}

// round 9
// speedup vs baseline: 1.4655x; 1.4655x over previous
#include <cuda_runtime.h>
#include <string.h>

#define TSTEPS 7
typedef unsigned long long u64;

// ---- constant image layout: u64 entries, each a duplicated (w,w) f32 pair ----
enum {
  CW_WI0 = 0,    // 4  Wih_up[:,0]
  CW_WI1 = 4,    // 4  Wih_up[:,1]
  CW_BU  = 8,    // 4  bih_up+bhh_up
  CW_WHU = 12,   // 16 Whh_up
  CW_W1  = 28,   // 32 W1
  CW_B1  = 60,   // 4  b1
  CW_W2  = 64,   // 16 W2
  CW_B2  = 80,   // 4  b2
  CW_WID = 84,   // 16 Wih_dn
  CW_WHD = 100,  // 16 Whh_dn
  CW_BD  = 116,  // 4  bih_dn+bhh_dn
  CW_WO  = 120,  // 4  Wo[0:4]
  CW_WOJ = 124,  // 1  Wo[4]
  CW_BO  = 125,  // 1  bo
  CW_N   = 126
};

__constant__ u64 cw[CW_N];
__device__ u64 g_prep[CW_N];

__device__ __forceinline__ u64 dup_dev(float v) {
    unsigned u = __float_as_uint(v);
    return ((u64)u << 32) | (u64)u;
}

__global__ void prep_kernel(const float* Wih_up, const float* Whh_up,
                            const float* bih_up, const float* bhh_up,
                            const float* W1, const float* b1,
                            const float* W2, const float* b2,
                            const float* Wih_dn, const float* Whh_dn,
                            const float* bih_dn, const float* bhh_dn,
                            const float* Wo, const float* bo)
{
    if (threadIdx.x != 0) return;
    for (int i = 0; i < 4; i++) {
        g_prep[CW_WI0 + i] = dup_dev(Wih_up[2*i]);
        g_prep[CW_WI1 + i] = dup_dev(Wih_up[2*i+1]);
        g_prep[CW_BU  + i] = dup_dev(bih_up[i] + bhh_up[i]);
        g_prep[CW_B1  + i] = dup_dev(b1[i]);
        g_prep[CW_B2  + i] = dup_dev(b2[i]);
        g_prep[CW_BD  + i] = dup_dev(bih_dn[i] + bhh_dn[i]);
        g_prep[CW_WO  + i] = dup_dev(Wo[i]);
    }
    for (int k = 0; k < 16; k++) {
        g_prep[CW_WHU + k] = dup_dev(Whh_up[k]);
        g_prep[CW_W2  + k] = dup_dev(W2[k]);
        g_prep[CW_WID + k] = dup_dev(Wih_dn[k]);
        g_prep[CW_WHD + k] = dup_dev(Whh_dn[k]);
    }
    for (int k = 0; k < 32; k++) g_prep[CW_W1 + k] = dup_dev(W1[k]);
    g_prep[CW_WOJ] = dup_dev(Wo[4]);
    g_prep[CW_BO]  = dup_dev(bo[0]);
}

// ---- f32x2 packed helpers ----
__device__ __forceinline__ u64 pack2(float lo, float hi) {
    u64 r; asm("mov.b64 %0, {%1, %2};" : "=l"(r) : "f"(lo), "f"(hi)); return r;
}
__device__ __forceinline__ void unpack2(u64 p, float& lo, float& hi) {
    asm("mov.b64 {%0, %1}, %2;" : "=f"(lo), "=f"(hi) : "l"(p));
}
__device__ __forceinline__ u64 fma2(u64 a, u64 b, u64 c) {
    u64 d; asm("fma.rn.f32x2 %0, %1, %2, %3;" : "=l"(d) : "l"(a), "l"(b), "l"(c)); return d;
}
__device__ __forceinline__ float htanh(float x) {
    float r; asm("tanh.approx.f32 %0, %1;" : "=f"(r) : "f"(x)); return r;
}
__device__ __forceinline__ u64 tanh2(u64 p) {
    float lo, hi; unpack2(p, lo, hi);
    return pack2(htanh(lo), htanh(hi));
}

// scalar fallback for tail rows (cold path, raw weights)
__device__ void scalar_row(int row, const float* x,
                           const float* Wih_up, const float* Whh_up,
                           const float* bih_up, const float* bhh_up,
                           const float* W1, const float* b1,
                           const float* W2, const float* b2,
                           const float* Wih_dn, const float* Whh_dn,
                           const float* bih_dn, const float* bhh_dn,
                           const float* Wo, const float* bo, float* out)
{
    float xr[18];
    for (int k = 0; k < 18; k++) xr[k] = x[(size_t)row * 18 + k];
    const float* obs = xr; const float* jj = xr + 4; const float* jjd = xr + 11;
    float h[4] = {0,0,0,0}, hup[TSTEPS][4];
    for (int s = 0; s < TSTEPS; s++) {
        int ti = TSTEPS - 1 - s;
        float pre[4];
        for (int i = 0; i < 4; i++) {
            float p = bih_up[i] + bhh_up[i];
            p = fmaf(Wih_up[i*2+0], jj[ti], p);
            p = fmaf(Wih_up[i*2+1], jjd[ti], p);
            for (int k = 0; k < 4; k++) p = fmaf(Whh_up[i*4+k], h[k], p);
            pre[i] = p;
        }
        for (int i = 0; i < 4; i++) { h[i] = htanh(pre[i]); hup[ti][i] = h[i]; }
    }
    float z[8]; for (int k = 0; k < 4; k++) { z[k] = obs[k]; z[4+k] = h[k]; }
    float h0[4];
    for (int i = 0; i < 4; i++) {
        float p = b1[i];
        for (int k = 0; k < 8; k++) p = fmaf(W1[i*8+k], z[k], p);
        h0[i] = htanh(p);
    }
    for (int i = 0; i < 4; i++) {
        float p = b2[i];
        for (int k = 0; k < 4; k++) p = fmaf(W2[i*4+k], h0[k], p);
        h[i] = htanh(p);
    }
    for (int t = 0; t < TSTEPS; t++) {
        float a = fmaf(Wo[4], jj[t], bo[0]);
        for (int k = 0; k < 4; k++) a = fmaf(Wo[k], h[k], a);
        out[(size_t)row * TSTEPS + t] = a;
        float hn[4];
        for (int i = 0; i < 4; i++) {
            float p = bih_dn[i] + bhh_dn[i];
            for (int k = 0; k < 4; k++) {
                p = fmaf(Wih_dn[i*4+k], hup[t][k], p);
                p = fmaf(Whh_dn[i*4+k], h[k], p);
            }
            hn[i] = htanh(p);
        }
        for (int i = 0; i < 4; i++) h[i] = hn[i];
    }
}

__global__ __launch_bounds__(128, 5)
void rec_policy_kernel(const float* __restrict__ x, float* __restrict__ out, int B,
                       const float* Wih_up, const float* Whh_up,
                       const float* bih_up, const float* bhh_up,
                       const float* W1, const float* b1,
                       const float* W2, const float* b2,
                       const float* Wih_dn, const float* Whh_dn,
                       const float* bih_dn, const float* bhh_dn,
                       const float* Wo, const float* bo)
{
    // Per-warp region [28 slots][32 lanes] u64 (7168B). The transient x-gather stage
    // (4608B = slots 0..17) overlays the hup slots: it is fully consumed into regs
    // (with a __syncwarp) before the first hup write (slot 24, descending to 0).
    __shared__ u64 sm[4 * 28 * 32];

    const int tid  = threadIdx.x;
    const int lane = tid & 31;
    const int wid  = tid >> 5;
    u64* wsm = sm + wid * (28 * 32);
    const int warpBase = (blockIdx.x * 128 + wid * 32) * 2;
    const int r0 = warpBase + lane * 2;

    const bool fast = (warpBase + 64 <= B);
    if (!fast) {
        if (r0 < B)     scalar_row(r0,   x, Wih_up, Whh_up, bih_up, bhh_up, W1, b1,
                                   W2, b2, Wih_dn, Whh_dn, bih_dn, bhh_dn, Wo, bo, out);
        if (r0 + 1 < B) scalar_row(r0+1, x, Wih_up, Whh_up, bih_up, bhh_up, W1, b1,
                                   W2, b2, Wih_dn, Whh_dn, bih_dn, bhh_dn, Wo, bo, out);
        return;
    }

    // ---- coalesced x gather into the overlay stage (slots 0..17) ----
    {
        const float4* g  = reinterpret_cast<const float4*>(x + (size_t)warpBase * 18);
        float4*       s4 = reinterpret_cast<float4*>(wsm);
        #pragma unroll
        for (int r = 0; r < 9; r++) s4[r * 32 + lane] = g[r * 32 + lane];
    }
    __syncwarp();

    // ---- read own 36 floats, pack row-pair X[18] (stays in registers) ----
    u64 X[18];
    {
        float xb[36];
        const float4* sp = reinterpret_cast<const float4*>(
            reinterpret_cast<const float*>(wsm) + lane * 36);
        #pragma unroll
        for (int k = 0; k < 9; k++) {
            float4 v = sp[k];
            xb[4*k] = v.x; xb[4*k+1] = v.y; xb[4*k+2] = v.z; xb[4*k+3] = v.w;
        }
        __syncwarp();
        #pragma unroll
        for (int j = 0; j < 18; j++) X[j] = pack2(xb[j], xb[18 + j]);
    }

    u64 h[4];
    #pragma unroll
    for (int i = 0; i < 4; i++) h[i] = 0ull;

    // ================= UP PHASE =================
    #pragma unroll
    for (int s = 0; s < TSTEPS; s++) {
        const int ti = TSTEPS - 1 - s;
        u64 jjv = X[4 + ti], jdv = X[11 + ti];
        u64 pre[4];
        #pragma unroll
        for (int i = 0; i < 4; i++) {
            u64 p = fma2(cw[CW_WI0 + i], jjv, cw[CW_BU + i]);
            p = fma2(cw[CW_WI1 + i], jdv, p);
            p = fma2(cw[CW_WHU + 4*i + 0], h[0], p);
            p = fma2(cw[CW_WHU + 4*i + 1], h[1], p);
            p = fma2(cw[CW_WHU + 4*i + 2], h[2], p);
            p = fma2(cw[CW_WHU + 4*i + 3], h[3], p);
            pre[i] = p;
        }
        #pragma unroll
        for (int i = 0; i < 4; i++) {
            h[i] = tanh2(pre[i]);
            wsm[(ti * 4 + i) * 32 + lane] = h[i];
        }
    }

    // ================= MLP PHASE =================
    {
        u64 h0[4];
        #pragma unroll
        for (int i = 0; i < 4; i++) {
            u64 p = cw[CW_B1 + i];
            p = fma2(cw[CW_W1 + 8*i + 0], X[0], p);
            p = fma2(cw[CW_W1 + 8*i + 1], X[1], p);
            p = fma2(cw[CW_W1 + 8*i + 2], X[2], p);
            p = fma2(cw[CW_W1 + 8*i + 3], X[3], p);
            p = fma2(cw[CW_W1 + 8*i + 4], h[0], p);
            p = fma2(cw[CW_W1 + 8*i + 5], h[1], p);
            p = fma2(cw[CW_W1 + 8*i + 6], h[2], p);
            p = fma2(cw[CW_W1 + 8*i + 7], h[3], p);
            h0[i] = tanh2(p);
        }
        #pragma unroll
        for (int i = 0; i < 4; i++) {
            u64 p = cw[CW_B2 + i];
            p = fma2(cw[CW_W2 + 4*i + 0], h0[0], p);
            p = fma2(cw[CW_W2 + 4*i + 1], h0[1], p);
            p = fma2(cw[CW_W2 + 4*i + 2], h0[2], p);
            p = fma2(cw[CW_W2 + 4*i + 3], h0[3], p);
            h[i] = tanh2(p);
        }
    }

    // ================= DOWN PHASE =================
    #pragma unroll
    for (int t = 0; t < TSTEPS; t++) {
        u64 hu0 = wsm[(t*4 + 0) * 32 + lane];
        u64 hu1 = wsm[(t*4 + 1) * 32 + lane];
        u64 hu2 = wsm[(t*4 + 2) * 32 + lane];
        u64 hu3 = wsm[(t*4 + 3) * 32 + lane];

        u64 a = fma2(cw[CW_WOJ], X[4 + t], cw[CW_BO]);
        a = fma2(cw[CW_WO + 0], h[0], a);
        a = fma2(cw[CW_WO + 1], h[1], a);
        a = fma2(cw[CW_WO + 2], h[2], a);
        a = fma2(cw[CW_WO + 3], h[3], a);
        wsm[(t*4 + 0) * 32 + lane] = a;      // park acts[t] in the consumed slot

        u64 hn[4];
        #pragma unroll
        for (int i = 0; i < 4; i++) {
            u64 p = cw[CW_BD + i];
            p = fma2(cw[CW_WID + 4*i + 0], hu0, p);
            p = fma2(cw[CW_WID + 4*i + 1], hu1, p);
            p = fma2(cw[CW_WID + 4*i + 2], hu2, p);
            p = fma2(cw[CW_WID + 4*i + 3], hu3, p);
            p = fma2(cw[CW_WHD + 4*i + 0], h[0], p);
            p = fma2(cw[CW_WHD + 4*i + 1], h[1], p);
            p = fma2(cw[CW_WHD + 4*i + 2], h[2], p);
            p = fma2(cw[CW_WHD + 4*i + 3], h[3], p);
            hn[i] = tanh2(p);
        }
        #pragma unroll
        for (int i = 0; i < 4; i++) h[i] = hn[i];
    }

    // ---- output flush: parked acts -> 14 contiguous floats per thread ----
    {
        float a0[TSTEPS], a1[TSTEPS];
        #pragma unroll
        for (int t = 0; t < TSTEPS; t++)
            unpack2(wsm[(t*4 + 0) * 32 + lane], a0[t], a1[t]);
        float2* o = reinterpret_cast<float2*>(out + (size_t)r0 * TSTEPS);
        o[0] = make_float2(a0[0], a0[1]);
        o[1] = make_float2(a0[2], a0[3]);
        o[2] = make_float2(a0[4], a0[5]);
        o[3] = make_float2(a0[6], a1[0]);
        o[4] = make_float2(a1[1], a1[2]);
        o[5] = make_float2(a1[3], a1[4]);
        o[6] = make_float2(a1[5], a1[6]);
    }
}

extern "C" void kernel_launch(void* const* d_in, const int* in_sizes, int n_in,
                              void* d_out, int out_size)
{
    const float* x      = (const float*)d_in[0];
    const float* Wih_up = (const float*)d_in[1];
    const float* Whh_up = (const float*)d_in[2];
    const float* bih_up = (const float*)d_in[3];
    const float* bhh_up = (const float*)d_in[4];
    const float* W1     = (const float*)d_in[5];
    const float* b1     = (const float*)d_in[6];
    const float* W2     = (const float*)d_in[7];
    const float* b2     = (const float*)d_in[8];
    const float* Wih_dn = (const float*)d_in[9];
    const float* Whh_dn = (const float*)d_in[10];
    const float* bih_dn = (const float*)d_in[11];
    const float* bhh_dn = (const float*)d_in[12];
    const float* Wo     = (const float*)d_in[13];
    const float* bo     = (const float*)d_in[14];
    float* out = (float*)d_out;

    int B = in_sizes[0] / 18;

    // node 1: weight preprocessing (dup pairs, fused biases) into g_prep
    prep_kernel<<<1, 32>>>(Wih_up, Whh_up, bih_up, bhh_up, W1, b1, W2, b2,
                           Wih_dn, Whh_dn, bih_dn, bhh_dn, Wo, bo);
    // node 2: publish to constant bank (D2D memcpy, graph-capturable)
    void* src = nullptr;
    cudaGetSymbolAddress(&src, g_prep);
    cudaMemcpyToSymbolAsync(cw, src, sizeof(u64) * CW_N, 0, cudaMemcpyDeviceToDevice);

    // node 3: main kernel
    int rowsPerBlock = 256;            // 128 threads x 2 rows
    int blocks = (B + rowsPerBlock - 1) / rowsPerBlock;
    rec_policy_kernel<<<blocks, 128>>>(x, out, B,
                                       Wih_up, Whh_up, bih_up, bhh_up, W1, b1,
                                       W2, b2, Wih_dn, Whh_dn, bih_dn, bhh_dn, Wo, bo);
}